// round 17
// baseline (speedup 1.0000x reference)
#include <cuda_runtime.h>
#include <cuda_fp16.h>
#include <math.h>
#include <stdint.h>

// ---------------- problem constants ----------------
#define Nn 32768
#define Dd 512
#define Kk 2048

// ---------------- GEMM tiling ----------------
#define MT 128                  // CTA M tile
#define NTL 128                 // CTA N tile
#define NSTAGE 4
#define TILE_B 16384            // 128 rows x 128B (64 halves) pre-swizzled
#define STB (2 * TILE_B)        // A tile + B tile per stage
#define DCP 8                   // d-pair chunks (64 halves each) per full D
#define NTILES (Kk / NTL)       // 16
#define GTOT (NTILES * DCP)     // 128
#define DYN_SMEM (NSTAGE * STB + 1024)
#define MTILES (Nn / MT)        // 256

// ---------------- device scratch (no allocation allowed) ----------------
__device__ __align__(16) unsigned char g_xa[(size_t)MTILES * DCP * TILE_B]; // 32MB swizzled fp16 Xn
__device__ __align__(16) unsigned char g_cb[(size_t)NTILES * DCP * TILE_B]; //  2MB swizzled fp16 C
__device__ float g_invn[Nn];
__device__ float g_cn2[Kk];
__device__ int4  g_cand[Nn];
__device__ int   g_idx[Nn];
__device__ int   g_cnt[Kk];
__device__ int   g_off[Kk];
__device__ int   g_cur[Kk];
__device__ int   g_list[Nn];
__device__ float g_dw[Kk * Dd];
__device__ float g_nsum;

// ---------------- PTX helpers ----------------
__device__ __forceinline__ uint32_t smem_u32(const void* p) {
    uint32_t a;
    asm("{ .reg .u64 t; cvta.to.shared.u64 t, %1; cvt.u32.u64 %0, t; }" : "=r"(a) : "l"(p));
    return a;
}
#define MBAR_INIT(mb, cnt) \
    asm volatile("mbarrier.init.shared.b64 [%0], %1;" :: "r"(mb), "r"(cnt) : "memory")
#define MBAR_EXPECT_TX(mb, bytes) \
    asm volatile("mbarrier.arrive.expect_tx.shared.b64 _, [%0], %1;" :: "r"(mb), "r"(bytes) : "memory")
#define MBAR_ARRIVE(mb) \
    asm volatile("mbarrier.arrive.shared.b64 _, [%0];" :: "r"(mb) : "memory")
#define MBAR_WAIT(mb, ph) do {                                                        \
    uint32_t _m = (mb), _p = (ph), _d;                                                \
    asm volatile("{\n\t.reg .pred p;\n\t"                                             \
        "mbarrier.try_wait.parity.acquire.cta.shared::cta.b64 p, [%1], %2;\n\t"       \
        "selp.b32 %0, 1, 0, p;\n\t}" : "=r"(_d) : "r"(_m), "r"(_p) : "memory");       \
    if (!_d) {                                                                        \
        asm volatile("{\n\t.reg .pred P1;\n\t"                                        \
            "WL_%=:\n\t"                                                              \
            "mbarrier.try_wait.parity.acquire.cta.shared::cta.b64 P1, [%0], %1, 0x989680;\n\t" \
            "@P1 bra.uni WD_%=;\n\tbra.uni WL_%=;\n\tWD_%=:\n\t}"                     \
            :: "r"(_m), "r"(_p) : "memory");                                          \
    } } while (0)

__device__ __forceinline__ void bulk_g2s(uint32_t dst, const void* src, uint32_t bytes, uint32_t mb) {
    asm volatile("cp.async.bulk.shared::cluster.global.mbarrier::complete_tx::bytes [%0], [%1], %2, [%3];"
                 :: "r"(dst), "l"(src), "r"(bytes), "r"(mb) : "memory");
}
__device__ __forceinline__ void ldmatrix_x4(uint32_t* r, uint32_t addr) {
    asm volatile("ldmatrix.sync.aligned.m8n8.x4.shared.b16 {%0,%1,%2,%3}, [%4];"
                 : "=r"(r[0]), "=r"(r[1]), "=r"(r[2]), "=r"(r[3]) : "r"(addr));
}
__device__ __forceinline__ void ldmatrix_x2(uint32_t* r, uint32_t addr) {
    asm volatile("ldmatrix.sync.aligned.m8n8.x2.shared.b16 {%0,%1}, [%2];"
                 : "=r"(r[0]), "=r"(r[1]) : "r"(addr));
}
__device__ __forceinline__ void mma16816(float* c, const uint32_t* a, const uint32_t* b) {
    asm volatile("mma.sync.aligned.m16n8k16.row.col.f32.f16.f16.f32 "
                 "{%0,%1,%2,%3}, {%4,%5,%6,%7}, {%8,%9}, {%0,%1,%2,%3};"
                 : "+f"(c[0]), "+f"(c[1]), "+f"(c[2]), "+f"(c[3])
                 : "r"(a[0]), "r"(a[1]), "r"(a[2]), "r"(a[3]), "r"(b[0]), "r"(b[1]));
}
__device__ __forceinline__ unsigned long long packkey(float s, int n) {
    unsigned u = __float_as_uint(s);
    u = (u & 0x80000000u) ? ~u : (u | 0x80000000u);
    return ((unsigned long long)u << 32) | (unsigned)n;
}
__device__ __forceinline__ void upd3(unsigned long long& t0, unsigned long long& t1,
                                     unsigned long long& t2, unsigned long long k) {
    if (k < t2) {
        if (k < t1) {
            t2 = t1;
            if (k < t0) { t1 = t0; t0 = k; } else { t1 = k; }
        } else { t2 = k; }
    }
}
static __device__ __forceinline__ uint32_t sw128(uint32_t off) {
    return off ^ ((off >> 3) & 0x70);
}

// ---------------- init counters ----------------
__global__ void k_init() {
    int t = threadIdx.x;
    for (int j = t; j < Kk; j += 256) { g_cnt[j] = 0; g_cur[j] = 0; }
}

// ---------------- fused rownorm + normalize + fp16 pack (swizzled) --------------
// one warp per row of X
__global__ void k_normpack(const float* __restrict__ X) {
    int row = (blockIdx.x * blockDim.x + threadIdx.x) >> 5;
    int lane = threadIdx.x & 31;
    const float4* xr = (const float4*)(X + (size_t)row * Dd);
    float4 v[4];
    double s = 0.0;
#pragma unroll
    for (int q = 0; q < 4; ++q) {
        v[q] = xr[lane * 4 + q];
        s += (double)v[q].x * v[q].x + (double)v[q].y * v[q].y
           + (double)v[q].z * v[q].z + (double)v[q].w * v[q].w;
    }
#pragma unroll
    for (int o = 16; o; o >>= 1) s += __shfl_down_sync(0xffffffffu, s, o);
    s = __shfl_sync(0xffffffffu, s, 0);
    double nrm = sqrt(s);
    if (nrm < 1e-12) nrm = 1e-12;
    float inv = (float)(1.0 / nrm);
    if (lane == 0) g_invn[row] = inv;

    // lane owns d in [lane*16, lane*16+16)
    int mt = row >> 7, r = row & 127;
    int dcp = lane >> 2;                 // d0/64
    int colb = (lane & 3) * 32;          // byte col within 128B row
    unsigned char* base = g_xa + (size_t)(mt * DCP + dcp) * TILE_B;
    uint32_t p[8];
#pragma unroll
    for (int q = 0; q < 4; ++q) {
        __half2 h0 = __floats2half2_rn(v[q].x * inv, v[q].y * inv);
        __half2 h1 = __floats2half2_rn(v[q].z * inv, v[q].w * inv);
        p[q * 2]     = *(uint32_t*)&h0;
        p[q * 2 + 1] = *(uint32_t*)&h1;
    }
    *(uint4*)(base + sw128((uint32_t)(r * 128 + colb)))      = make_uint4(p[0], p[1], p[2], p[3]);
    *(uint4*)(base + sw128((uint32_t)(r * 128 + colb + 16))) = make_uint4(p[4], p[5], p[6], p[7]);
}

// ---------------- fused cnorm + fp16 pack (swizzled) ----------------------------
__global__ void k_cpack(const float* __restrict__ C) {
    int row = (blockIdx.x * blockDim.x + threadIdx.x) >> 5;
    int lane = threadIdx.x & 31;
    const float4* cr = (const float4*)(C + (size_t)row * Dd);
    float4 v[4];
    double s = 0.0;
#pragma unroll
    for (int q = 0; q < 4; ++q) {
        v[q] = cr[lane * 4 + q];
        s += (double)v[q].x * v[q].x + (double)v[q].y * v[q].y
           + (double)v[q].z * v[q].z + (double)v[q].w * v[q].w;
    }
#pragma unroll
    for (int o = 16; o; o >>= 1) s += __shfl_down_sync(0xffffffffu, s, o);
    if (lane == 0) g_cn2[row] = (float)s;

    int nt = row >> 7, r = row & 127;
    int dcp = lane >> 2;
    int colb = (lane & 3) * 32;
    unsigned char* base = g_cb + (size_t)(nt * DCP + dcp) * TILE_B;
    uint32_t p[8];
#pragma unroll
    for (int q = 0; q < 4; ++q) {
        __half2 h0 = __floats2half2_rn(v[q].x, v[q].y);
        __half2 h1 = __floats2half2_rn(v[q].z, v[q].w);
        p[q * 2]     = *(uint32_t*)&h0;
        p[q * 2 + 1] = *(uint32_t*)&h1;
    }
    *(uint4*)(base + sw128((uint32_t)(r * 128 + colb)))      = make_uint4(p[0], p[1], p[2], p[3]);
    *(uint4*)(base + sw128((uint32_t)(r * 128 + colb + 16))) = make_uint4(p[4], p[5], p[6], p[7]);
}

// ---------------- HMMA GEMM + top-3 selection, bulk-copy pipeline ---------------
// 288 threads: warps 0-7 compute (2x4 grid, warp tile 64x32), warp 8 producer.
__global__ __launch_bounds__(288, 1) void k_hmma() {
    extern __shared__ char dsm[];
    __shared__ __align__(8) unsigned long long s_mbar[8];  // full[4] @0, empty[4] @32
    __shared__ float scn[Kk];

    const int tid = threadIdx.x, lane = tid & 31, wid = tid >> 5;
    uint32_t dbase = smem_u32(dsm);
    dbase = (dbase + 1023) & ~1023u;
    const uint32_t mb = smem_u32(s_mbar);
    const int mt0 = blockIdx.x;

    for (int i = tid; i < Kk; i += 288) scn[i] = g_cn2[i];
    if (tid == 0) {
#pragma unroll
        for (int s = 0; s < NSTAGE; ++s) {
            MBAR_INIT(mb + s * 8, 1);          // full[s]: tx-based
            MBAR_INIT(mb + 32 + s * 8, 8);     // empty[s]: 8 consumer warps
        }
    }
    __syncthreads();

    if (wid == 8) {
        // ---------------- producer ----------------
        if (lane == 0) {
            for (int g = 0; g < GTOT; ++g) {
                int s = g & (NSTAGE - 1), u = g >> 2;
                MBAR_WAIT(mb + 32 + s * 8, (u & 1) ^ 1);     // empty[s]
                uint32_t fb = mb + s * 8;
                MBAR_EXPECT_TX(fb, STB);
                uint32_t sb = dbase + s * STB;
                bulk_g2s(sb,          g_xa + (size_t)(mt0 * DCP + (g & 7)) * TILE_B, TILE_B, fb);
                bulk_g2s(sb + TILE_B, g_cb + (size_t)((g >> 3) * DCP + (g & 7)) * TILE_B, TILE_B, fb);
            }
        }
    } else {
        // ---------------- compute warps ----------------
        const int wm = wid >> 2, wn = wid & 3;
        const int mwbase = wm * 64, nwbase = wn * 32;
        const int l = lane & 15;

        unsigned long long t0[8], t1[8], t2[8];
#pragma unroll
        for (int r = 0; r < 8; ++r) { t0[r] = ~0ull; t1[r] = ~0ull; t2[r] = ~0ull; }

        int g = 0;
        for (int nt = 0; nt < NTILES; ++nt) {
            float acc[4][4][4];
#pragma unroll
            for (int mt = 0; mt < 4; ++mt)
#pragma unroll
                for (int nb = 0; nb < 4; ++nb)
#pragma unroll
                    for (int e = 0; e < 4; ++e) acc[mt][nb][e] = 0.0f;

            for (int dcp = 0; dcp < DCP; ++dcp, ++g) {
                int s = g & (NSTAGE - 1), u = g >> 2;
                MBAR_WAIT(mb + s * 8, u & 1);                 // full[s]
                uint32_t uA = dbase + s * STB;
                uint32_t uB = uA + TILE_B;
#pragma unroll
                for (int k16 = 0; k16 < 4; ++k16) {
                    uint32_t afr[4][4], bfr[4][2];
                    int kbA = (k16 * 16 + (lane >> 4) * 8) * 2;
#pragma unroll
                    for (int mt = 0; mt < 4; ++mt) {
                        uint32_t off = (uint32_t)((mwbase + mt * 16 + l) * 128 + kbA);
                        ldmatrix_x4(afr[mt], uA + sw128(off));
                    }
                    int kbB = (k16 * 16 + ((l >> 3) & 1) * 8) * 2;
#pragma unroll
                    for (int nb = 0; nb < 4; ++nb) {
                        uint32_t off = (uint32_t)((nwbase + nb * 8 + (l & 7)) * 128 + kbB);
                        ldmatrix_x2(bfr[nb], uB + sw128(off));
                    }
#pragma unroll
                    for (int mt = 0; mt < 4; ++mt)
#pragma unroll
                        for (int nb = 0; nb < 4; ++nb)
                            mma16816(acc[mt][nb], afr[mt], bfr[nb]);
                }
                if (lane == 0) MBAR_ARRIVE(mb + 32 + s * 8);  // empty[s]
            }

            // fold scores into per-row top-3
#pragma unroll
            for (int mt = 0; mt < 4; ++mt) {
#pragma unroll
                for (int nb = 0; nb < 4; ++nb) {
                    int n0 = nt * NTL + nwbase + nb * 8 + 2 * (lane & 3);
                    float cnA = scn[n0], cnB = scn[n0 + 1];
                    upd3(t0[mt * 2],     t1[mt * 2],     t2[mt * 2],
                         packkey(cnA - 2.0f * acc[mt][nb][0], n0));
                    upd3(t0[mt * 2],     t1[mt * 2],     t2[mt * 2],
                         packkey(cnB - 2.0f * acc[mt][nb][1], n0 + 1));
                    upd3(t0[mt * 2 + 1], t1[mt * 2 + 1], t2[mt * 2 + 1],
                         packkey(cnA - 2.0f * acc[mt][nb][2], n0));
                    upd3(t0[mt * 2 + 1], t1[mt * 2 + 1], t2[mt * 2 + 1],
                         packkey(cnB - 2.0f * acc[mt][nb][3], n0 + 1));
                }
            }
        }

        __syncthreads();   // (A)
        // merge: 16 participants per row x 3 keys, staged in (now idle) dsm
        unsigned long long* mk = (unsigned long long*)dsm;
#pragma unroll
        for (int rs = 0; rs < 8; ++rs) {
            int ml = wm * 64 + (rs >> 1) * 16 + (rs & 1) * 8 + (lane >> 2);
            int p = wn * 4 + (lane & 3);
            unsigned long long* d = mk + (size_t)(ml * 16 + p) * 3;
            d[0] = t0[rs]; d[1] = t1[rs]; d[2] = t2[rs];
        }
        __syncthreads();   // (B)
        if (tid < MT) {
            unsigned long long a = ~0ull, b = ~0ull, c = ~0ull;
            const unsigned long long* sK = mk + (size_t)tid * 48;
            for (int j = 0; j < 48; ++j) upd3(a, b, c, sK[j]);
            g_cand[mt0 * MT + tid] = make_int4((int)(unsigned)a, (int)(unsigned)b, (int)(unsigned)c, 0);
        }
        return;   // compute warps exit (named barriers below are producer-free)
    }
    // producer warp: participate in the two barriers the compute warps hit
    __syncthreads();   // (A)
    __syncthreads();   // (B)
}

// ---------------- exact fp32 refine over 3 candidates + histogram + quant -------
__global__ void k_refine(const float* __restrict__ X, const float* __restrict__ C,
                         float* __restrict__ oIdx, float* __restrict__ oQ) {
    int wid = threadIdx.x >> 5, lane = threadIdx.x & 31;
    int row = blockIdx.x * 8 + wid;
    int4 cd = g_cand[row];
    const float4* xr = (const float4*)(X + (size_t)row * Dd);
    const float4* c0 = (const float4*)(C + (size_t)cd.x * Dd);
    const float4* c1 = (const float4*)(C + (size_t)cd.y * Dd);
    const float4* c2 = (const float4*)(C + (size_t)cd.z * Dd);
    float s0 = 0.f, s1 = 0.f, s2 = 0.f;
#pragma unroll
    for (int e = lane; e < Dd / 4; e += 32) {
        float4 x = xr[e];
        float4 a = c0[e], b = c1[e], c = c2[e];
        s0 = fmaf(x.x, a.x, fmaf(x.y, a.y, fmaf(x.z, a.z, fmaf(x.w, a.w, s0))));
        s1 = fmaf(x.x, b.x, fmaf(x.y, b.y, fmaf(x.z, b.z, fmaf(x.w, b.w, s1))));
        s2 = fmaf(x.x, c.x, fmaf(x.y, c.y, fmaf(x.z, c.z, fmaf(x.w, c.w, s2))));
    }
#pragma unroll
    for (int o = 16; o; o >>= 1) {
        s0 += __shfl_down_sync(0xffffffffu, s0, o);
        s1 += __shfl_down_sync(0xffffffffu, s1, o);
        s2 += __shfl_down_sync(0xffffffffu, s2, o);
    }
    int bi;
    if (lane == 0) {
        float inv = g_invn[row];
        float d0 = g_cn2[cd.x] - 2.0f * inv * s0;
        float d1 = g_cn2[cd.y] - 2.0f * inv * s1;
        float d2 = g_cn2[cd.z] - 2.0f * inv * s2;
        float bv = d0; bi = cd.x;
        if (d1 < bv || (d1 == bv && cd.y < bi)) { bv = d1; bi = cd.y; }
        if (d2 < bv || (d2 == bv && cd.z < bi)) { bv = d2; bi = cd.z; }
        g_idx[row] = bi;
        oIdx[row] = (float)bi;
        atomicAdd(&g_cnt[bi], 1);
    }
    bi = __shfl_sync(0xffffffffu, bi, 0);
    // gather quantized row (C row is hot in L1/L2 from the refine reads)
    const float4* cw = (const float4*)(C + (size_t)bi * Dd);
    float4* qw = (float4*)(oQ + (size_t)row * Dd);
#pragma unroll
    for (int e = lane; e < Dd / 4; e += 32) qw[e] = cw[e];
}

// ---------------- scan / fill / per-cluster reduce ----------------
__global__ void k_scan() {
    __shared__ int part[256];
    int t = threadIdx.x;
    int loc[8];
    int sum = 0;
#pragma unroll
    for (int i = 0; i < 8; ++i) {
        int c = g_cnt[t * 8 + i];
        loc[i] = sum; sum += c;
    }
    part[t] = sum;
    __syncthreads();
    int total = sum;
    for (int o = 1; o < 256; o <<= 1) {
        int v = (t >= o) ? part[t - o] : 0;
        __syncthreads();
        part[t] += v;
        __syncthreads();
    }
    int excl = part[t] - total;
#pragma unroll
    for (int i = 0; i < 8; ++i) g_off[t * 8 + i] = excl + loc[i];
}
__global__ void k_fill() {
    int i = blockIdx.x * 256 + threadIdx.x;
    if (i < Nn) {
        int k = g_idx[i];
        int pos = atomicAdd(&g_cur[k], 1);
        g_list[g_off[k] + pos] = i;
    }
}
__global__ void k_dw(const float* __restrict__ X) {
    int k = blockIdx.x;
    int cnt = g_cnt[k], off = g_off[k];
    int t = threadIdx.x;                 // 256 threads, 2 floats each
    float2 acc = make_float2(0.f, 0.f);
    for (int j = 0; j < cnt; ++j) {
        int row = g_list[off + j];
        float2 v = ((const float2*)(X + (size_t)row * Dd))[t];
        acc.x += v.x; acc.y += v.y;
    }
    ((float2*)(g_dw + (size_t)k * Dd))[t] = acc;
}

// ---------------- n = sum_k (ema_size*0.99 + 0.01*count) ----------------
__global__ void k_reduce(const float* __restrict__ ES) {
    __shared__ float sh[256];
    int tid = threadIdx.x;
    float s = 0.0f;
    for (int i = tid; i < Kk; i += 256)
        s += ES[i] * 0.99f + 0.01f * (float)g_cnt[i];
    sh[tid] = s;
    __syncthreads();
    for (int o = 128; o; o >>= 1) {
        if (tid < o) sh[tid] += sh[tid + o];
        __syncthreads();
    }
    if (tid == 0) g_nsum = sh[0];
}

// ---------------- finalize EMA outputs ----------------
__global__ void k_finalize(const float* __restrict__ ES, const float* __restrict__ EW,
                           float* __restrict__ oC, float* __restrict__ oS,
                           float* __restrict__ oW)
{
    int i = blockIdx.x * 256 + threadIdx.x;
    int k = i >> 9;
    float nw  = EW[i] * 0.99f + 0.01f * g_dw[i];
    float pre = ES[k] * 0.99f + 0.01f * (float)g_cnt[k];
    float nt  = g_nsum;
    float ns  = (pre + 1e-5f) / (nt + 2048.0f * 1e-5f) * nt;
    oW[i] = nw;
    oC[i] = nw / ns;
    if ((i & 511) == 0) oS[k] = ns;
}

// ---------------- launch ----------------
extern "C" void kernel_launch(void* const* d_in, const int* in_sizes, int n_in,
                              void* d_out, int out_size)
{
    const float* X  = (const float*)d_in[0];   // [N, D]
    const float* C  = (const float*)d_in[1];   // [K, D]
    const float* ES = (const float*)d_in[2];   // [K]
    const float* EW = (const float*)d_in[3];   // [K, D]

    float* out = (float*)d_out;
    float* oQ = out;                               // quantized     N*D
    float* oI = oQ + (size_t)Nn * Dd;              // indices       N
    float* oC = oI + Nn;                           // new_centroids K*D
    float* oS = oC + (size_t)Kk * Dd;              // new_size      K
    float* oW = oS + Kk;                           // new_w         K*D

    cudaFuncSetAttribute(k_hmma, cudaFuncAttributeMaxDynamicSharedMemorySize, DYN_SMEM);

    k_init<<<1, 256>>>();
    k_normpack<<<(Nn * 32) / 256, 256>>>(X);
    k_cpack<<<(Kk * 32) / 256, 256>>>(C);
    k_hmma<<<MTILES, 288, DYN_SMEM>>>();
    k_refine<<<Nn / 8, 256>>>(X, C, oI, oQ);
    k_scan<<<1, 256>>>();
    k_fill<<<Nn / 256, 256>>>();
    k_dw<<<Kk, 256>>>(X);
    k_reduce<<<1, 256>>>(ES);
    k_finalize<<<(Kk * Dd) / 256, 256>>>(ES, EW, oC, oS, oW);
}